// round 8
// baseline (speedup 1.0000x reference)
#include <cuda_runtime.h>

typedef unsigned long long ull;

#define NPOINTS 32768
#define HW      4096
#define NCODES  8192
#define NSLICE  8
#define KSLICE  (NCODES / NSLICE)   // 1024 codes per slice
#define PAIRS   (KSLICE / 2)        // 512 code-pairs per slice
#define T1      128                 // threads per CTA, kernel 1
#define PPT     2                   // points per thread (low reg pressure)
#define PGROUPS (NPOINTS / (T1 * PPT))  // 128  -> grid = 1024 CTAs (single wave)
#define FBLOCKS (NPOINTS / 256)     // 128 finalize blocks

// Scratch (device globals — no allocation allowed in kernel_launch)
__device__ float g_best[NSLICE * NPOINTS];
__device__ int   g_idx [NSLICE * NPOINTS];
__device__ float g_partial[FBLOCKS];

// ---- packed f32x2 helpers (sm_103a); per-lane IEEE rn, same as scalar ----
__device__ __forceinline__ ull fma2(ull a, ull b, ull c) {
    ull d;
    asm("fma.rn.f32x2 %0, %1, %2, %3;" : "=l"(d) : "l"(a), "l"(b), "l"(c));
    return d;
}
__device__ __forceinline__ ull add2(ull a, ull b) {
    ull d;
    asm("add.rn.f32x2 %0, %1, %2;" : "=l"(d) : "l"(a), "l"(b));
    return d;
}
__device__ __forceinline__ ull mul2(ull a, ull b) {
    ull d;
    asm("mul.rn.f32x2 %0, %1, %2;" : "=l"(d) : "l"(a), "l"(b));
    return d;
}
__device__ __forceinline__ ull pack2(float lo, float hi) {
    ull d;
    asm("mov.b64 %0, {%1, %2};" : "=l"(d) : "f"(lo), "f"(hi));
    return d;
}
__device__ __forceinline__ void unpack2(ull v, float& lo, float& hi) {
    asm("mov.b64 {%0, %1}, %2;" : "=f"(lo), "=f"(hi) : "l"(v));
}

// Reference fp32 1x1-conv einsum + bias, XLA/cuBLAS association:
//   dot = ascending-k FFMA chain starting from x0*w0; z = dot + b (bias LAST).
__device__ __forceinline__ void compute_z(
    const float* __restrict__ zin, const float* w /*16*/,
    const float* bb /*4*/, int p, float z[4])
{
    int b = p >> 12, hw = p & (HW - 1);
    const float* base = zin + b * (4 * HW) + hw;
    float x0 = base[0], x1 = base[HW], x2 = base[2 * HW], x3 = base[3 * HW];
#pragma unroll
    for (int o = 0; o < 4; o++) {
        float acc = __fmul_rn(x0, w[o * 4 + 0]);
        acc = __fmaf_rn(x1, w[o * 4 + 1], acc);
        acc = __fmaf_rn(x2, w[o * 4 + 2], acc);
        acc = __fmaf_rn(x3, w[o * 4 + 3], acc);
        z[o] = __fadd_rn(acc, bb[o]);
    }
}

// sum of squares, XLA style: elementwise multiply THEN sequential add (no FMA)
__device__ __forceinline__ float sumsq4(float a, float b, float c, float d) {
    float m0 = __fmul_rn(a, a), m1 = __fmul_rn(b, b);
    float m2 = __fmul_rn(c, c), m3 = __fmul_rn(d, d);
    return __fadd_rn(__fadd_rn(__fadd_rn(m0, m1), m2), m3);
}

// ============================================================================
// Kernel 1: per (point-group, code-slice) CTA — scan 1024 codes for 256 points.
// Exact reference fp32 association:
//   dot  = fma(z3,c3, fma(z2,c2, fma(z1,c1, z0*c0)))     (SGEMM ascending k)
//   d2   = (szz - 2*dot) + scc                            (left-to-right)
// PPT=2 keeps the live register set small so ptxas can hoist the next pair's
// LDS ahead and sink SELs away from their FSETPs (in-order issue exposure was
// the R5-R7 binder). Argmin: even/odd streams, FMNMX-carried min.
// smem pair layout (12 floats = 48B): [2d+ln] = c_{2pr+ln}[d], [8+ln] = ||c||^2
// ============================================================================
__global__ __launch_bounds__(T1, 8) void vq_search(
    const float* __restrict__ zin,   // [8,4,64,64]
    const float* __restrict__ Wm,    // [4,4]
    const float* __restrict__ bv,    // [4]
    const float* __restrict__ cb)    // [8192,4]
{
    __shared__ float s[PAIRS * 12];
    __shared__ float wq[16], bb[4];
    const int tid   = threadIdx.x;
    const int pg    = blockIdx.x;   // 0..127
    const int slice = blockIdx.y;   // 0..7
    const int k0    = slice * KSLICE;

    if (tid < 16) wq[tid] = __ldg(Wm + tid);
    if (tid < 4)  bb[tid] = __ldg(bv + tid);

    // Build codebook slice + fp32 |c|^2 (mul-then-add order) in smem
    for (int kk = tid; kk < KSLICE; kk += T1) {
        float4 c = ((const float4*)cb)[k0 + kk];
        int pr = kk >> 1, ln = kk & 1;
        float* d = s + pr * 12;
        d[0 + ln] = c.x;
        d[2 + ln] = c.y;
        d[4 + ln] = c.z;
        d[6 + ln] = c.w;
        d[8 + ln] = sumsq4(c.x, c.y, c.z, c.w);
    }
    __syncthreads();

    ull zz[PPT][4];   // z_d duplicated in both halves
    ull szz2[PPT];    // ||z||^2 duplicated
    int pts[PPT];
#pragma unroll
    for (int j = 0; j < PPT; j++) {
        int p = pg * (T1 * PPT) + j * T1 + tid;  // coalesced over tid
        pts[j] = p;
        float z[4];
        compute_z(zin, wq, bb, p, z);
        float szz = sumsq4(z[0], z[1], z[2], z[3]);
        szz2[j] = pack2(szz, szz);
#pragma unroll
        for (int o = 0; o < 4; o++) zz[j][o] = pack2(z[o], z[o]);
    }

    const ull neg2 = pack2(-2.0f, -2.0f);

    // Independent even(0)/odd(1) candidate streams per point: 4 chains/thread
    float best0[PPT], best1[PPT];
    int   bi0[PPT],   bi1[PPT];
#pragma unroll
    for (int j = 0; j < PPT; j++) {
        best0[j] = 3.4e38f; best1[j] = 3.4e38f; bi0[j] = 0; bi1[j] = 0;
    }

#pragma unroll 8
    for (int pr = 0; pr < PAIRS; ++pr) {
        const ull* q = (const ull*)(s + pr * 12);  // 48B stride, 16B aligned
        ull m0 = q[0], m1 = q[1], m2 = q[2], m3 = q[3], cc = q[4];
#pragma unroll
        for (int j = 0; j < PPT; j++) {
            // SGEMM-order dot product (mul == fma-with-zero, ascending k)
            ull dot = mul2(zz[j][0], m0);
            dot = fma2(zz[j][1], m1, dot);
            dot = fma2(zz[j][2], m2, dot);
            dot = fma2(zz[j][3], m3, dot);
            // t = szz - 2*dot (2*dot exact => single rounding); d2 = t + scc
            ull t  = fma2(dot, neg2, szz2[j]);
            ull d2 = add2(t, cc);
            float s0, s1;
            unpack2(d2, s0, s1);
            // FMNMX carries the running min; FSETP feeds index SEL only.
            // strict < => on tie keeps old (first-occurrence within stream).
            bool p0 = (s0 < best0[j]);
            bool p1 = (s1 < best1[j]);
            best0[j] = fminf(best0[j], s0);
            best1[j] = fminf(best1[j], s1);
            bi0[j] = p0 ? pr : bi0[j];
            bi1[j] = p1 ? pr : bi1[j];
        }
    }

#pragma unroll
    for (int j = 0; j < PPT; j++) {
        // Merge streams with exact first-index tie semantics:
        // winner = smaller d2; on exact tie, smaller k.
        int   ke0 = 2 * bi0[j], ke1 = 2 * bi1[j] + 1;
        float b0 = best0[j], b1 = best1[j];
        bool take1 = (b1 < b0) || (b1 == b0 && ke1 < ke0);
        float bw = take1 ? b1 : b0;
        int   kw = take1 ? ke1 : ke0;
        g_best[slice * NPOINTS + pts[j]] = bw;
        g_idx [slice * NPOINTS + pts[j]] = k0 + kw;
    }
}

// ============================================================================
// Kernel 2: per-point 8-way argmin across slices, gather code, write latent
// (z + (zq - z), reference's straight-through rounding), loss partials.
// ============================================================================
__global__ __launch_bounds__(256) void vq_finalize(
    const float* __restrict__ zin,
    const float* __restrict__ Wm,
    const float* __restrict__ bv,
    const float* __restrict__ cb,
    float* __restrict__ out)
{
    __shared__ float wq[16], bb[4];
    if (threadIdx.x < 16) wq[threadIdx.x] = __ldg(Wm + threadIdx.x);
    if (threadIdx.x < 4)  bb[threadIdx.x] = __ldg(bv + threadIdx.x);
    __syncthreads();

    const int p  = blockIdx.x * 256 + threadIdx.x;
    const int b  = p >> 12;
    const int hw = p & (HW - 1);

    float z[4];
    compute_z(zin, wq, bb, p, z);

    float bestv = 3.4e38f;
    int   idx   = 0;
#pragma unroll
    for (int sl = 0; sl < NSLICE; sl++) {
        float v = g_best[sl * NPOINTS + p];
        int   i = g_idx [sl * NPOINTS + p];
        if (v < bestv) { bestv = v; idx = i; }  // ascending slices: first-index ties
    }

    float4 c = ((const float4*)cb)[idx];
    float* ob = out + b * (4 * HW) + hw;
    // straight-through: z + (zq - z), two roundings, as in the reference
    float r0 = __fadd_rn(c.x, -z[0]);
    float r1 = __fadd_rn(c.y, -z[1]);
    float r2 = __fadd_rn(c.z, -z[2]);
    float r3 = __fadd_rn(c.w, -z[3]);
    ob[0]      = __fadd_rn(z[0], r0);
    ob[HW]     = __fadd_rn(z[1], r1);
    ob[2 * HW] = __fadd_rn(z[2], r2);
    ob[3 * HW] = __fadd_rn(z[3], r3);

    float acc = sumsq4(r0, r1, r2, r3);

    __shared__ float red[256];
    red[threadIdx.x] = acc;
    __syncthreads();
#pragma unroll
    for (int st = 128; st > 0; st >>= 1) {
        if (threadIdx.x < st) red[threadIdx.x] += red[threadIdx.x + st];
        __syncthreads();
    }
    if (threadIdx.x == 0) g_partial[blockIdx.x] = red[0];
}

// ============================================================================
// Kernel 3: deterministic final reduction of loss partials.
// q_loss = codebook_loss + BETA*commitment_loss = (1+0.25)*mean((zq-z)^2)
// ============================================================================
__global__ void vq_loss(float* __restrict__ out, int loss_idx)
{
    __shared__ float red[128];
    float a = g_partial[threadIdx.x];  // FBLOCKS == 128
    red[threadIdx.x] = a;
    __syncthreads();
#pragma unroll
    for (int st = 64; st > 0; st >>= 1) {
        if (threadIdx.x < st) red[threadIdx.x] += red[threadIdx.x + st];
        __syncthreads();
    }
    if (threadIdx.x == 0)
        out[loss_idx] = red[0] * (1.25f / (float)(NPOINTS * 4));
}

extern "C" void kernel_launch(void* const* d_in, const int* in_sizes, int n_in,
                              void* d_out, int out_size)
{
    const float* zin = (const float*)d_in[0];  // z_e_in [8,4,64,64]
    const float* Wm  = (const float*)d_in[1];  // pq_w [4,4]
    const float* bv  = (const float*)d_in[2];  // pq_b [4]
    const float* cb  = (const float*)d_in[3];  // codebook [8192,4]
    float* out = (float*)d_out;

    dim3 g1(PGROUPS, NSLICE);
    vq_search<<<g1, T1>>>(zin, Wm, bv, cb);
    vq_finalize<<<FBLOCKS, 256>>>(zin, Wm, bv, cb, out);
    vq_loss<<<1, 128>>>(out, out_size - 1);
}

// round 9
// speedup vs baseline: 1.6321x; 1.6321x over previous
#include <cuda_runtime.h>

typedef unsigned long long ull;

#define NPOINTS 32768
#define HW      4096
#define NCODES  8192
#define NSLICE  32
#define KSLICE  (NCODES / NSLICE)   // 256 codes per slice
#define PAIRS   (KSLICE / 2)        // 128 code-pairs per slice
#define T1      64                  // threads per CTA (2 warps) — fine-grained drain
#define PPT     4                   // points per thread
#define PGROUPS (NPOINTS / (T1 * PPT))  // 128  -> grid = 4096 CTAs
#define FBLOCKS (NPOINTS / 256)     // 128 finalize blocks

// Scratch (device globals — no allocation allowed in kernel_launch)
__device__ float2 g_bi[NSLICE * NPOINTS];  // (.x = best d2, .y = idx bits)
__device__ float  g_partial[FBLOCKS];

// ---- packed f32x2 helpers (sm_103a); per-lane IEEE rn, same as scalar ----
__device__ __forceinline__ ull fma2(ull a, ull b, ull c) {
    ull d;
    asm("fma.rn.f32x2 %0, %1, %2, %3;" : "=l"(d) : "l"(a), "l"(b), "l"(c));
    return d;
}
__device__ __forceinline__ ull add2(ull a, ull b) {
    ull d;
    asm("add.rn.f32x2 %0, %1, %2;" : "=l"(d) : "l"(a), "l"(b));
    return d;
}
__device__ __forceinline__ ull mul2(ull a, ull b) {
    ull d;
    asm("mul.rn.f32x2 %0, %1, %2;" : "=l"(d) : "l"(a), "l"(b));
    return d;
}
__device__ __forceinline__ ull pack2(float lo, float hi) {
    ull d;
    asm("mov.b64 %0, {%1, %2};" : "=l"(d) : "f"(lo), "f"(hi));
    return d;
}
__device__ __forceinline__ void unpack2(ull v, float& lo, float& hi) {
    asm("mov.b64 {%0, %1}, %2;" : "=f"(lo), "=f"(hi) : "l"(v));
}

// Reference fp32 1x1-conv einsum + bias, XLA/cuBLAS association:
//   dot = ascending-k FFMA chain starting from x0*w0; z = dot + b (bias LAST).
__device__ __forceinline__ void compute_z(
    const float* __restrict__ zin, const float* w /*16*/,
    const float* bb /*4*/, int p, float z[4])
{
    int b = p >> 12, hw = p & (HW - 1);
    const float* base = zin + b * (4 * HW) + hw;
    float x0 = base[0], x1 = base[HW], x2 = base[2 * HW], x3 = base[3 * HW];
#pragma unroll
    for (int o = 0; o < 4; o++) {
        float acc = __fmul_rn(x0, w[o * 4 + 0]);
        acc = __fmaf_rn(x1, w[o * 4 + 1], acc);
        acc = __fmaf_rn(x2, w[o * 4 + 2], acc);
        acc = __fmaf_rn(x3, w[o * 4 + 3], acc);
        z[o] = __fadd_rn(acc, bb[o]);
    }
}

// sum of squares, XLA style: elementwise multiply THEN sequential add (no FMA)
__device__ __forceinline__ float sumsq4(float a, float b, float c, float d) {
    float m0 = __fmul_rn(a, a), m1 = __fmul_rn(b, b);
    float m2 = __fmul_rn(c, c), m3 = __fmul_rn(d, d);
    return __fadd_rn(__fadd_rn(__fadd_rn(m0, m1), m2), m3);
}

// ============================================================================
// Kernel 1: per (point-group, code-slice) CTA — scan 256 codes for 256 points.
// Exact reference fp32 association:
//   dot  = fma(z3,c3, fma(z2,c2, fma(z1,c1, z0*c0)))     (SGEMM ascending k)
//   d2   = (szz - 2*dot) + scc                            (left-to-right)
// 2-warp CTAs, 4096 of them: fine-grained draining minimizes wave-tail idle
// (the measured occupancy killer). FMNMX carries the min; FSETP feeds SEL only.
// smem pair layout (12 floats = 48B): [2d+ln] = c_{2pr+ln}[d], [8+ln] = ||c||^2
// ============================================================================
__global__ __launch_bounds__(T1) void vq_search(
    const float* __restrict__ zin,   // [8,4,64,64]
    const float* __restrict__ Wm,    // [4,4]
    const float* __restrict__ bv,    // [4]
    const float* __restrict__ cb)    // [8192,4]
{
    __shared__ float s[PAIRS * 12];
    __shared__ float wq[16], bb[4];
    const int tid   = threadIdx.x;
    const int pg    = blockIdx.x;   // 0..127
    const int slice = blockIdx.y;   // 0..31
    const int k0    = slice * KSLICE;

    if (tid < 16) wq[tid] = __ldg(Wm + tid);
    if (tid < 4)  bb[tid] = __ldg(bv + tid);

    // Build codebook slice + fp32 |c|^2 (mul-then-add order) in smem
#pragma unroll
    for (int kk = tid; kk < KSLICE; kk += T1) {
        float4 c = ((const float4*)cb)[k0 + kk];
        int pr = kk >> 1, ln = kk & 1;
        float* d = s + pr * 12;
        d[0 + ln] = c.x;
        d[2 + ln] = c.y;
        d[4 + ln] = c.z;
        d[6 + ln] = c.w;
        d[8 + ln] = sumsq4(c.x, c.y, c.z, c.w);
    }
    __syncthreads();

    ull zz[PPT][4];   // z_d duplicated in both halves
    ull szz2[PPT];    // ||z||^2 duplicated
#pragma unroll
    for (int j = 0; j < PPT; j++) {
        int p = pg * (T1 * PPT) + j * T1 + tid;  // coalesced over tid
        float z[4];
        compute_z(zin, wq, bb, p, z);
        float szz = sumsq4(z[0], z[1], z[2], z[3]);
        szz2[j] = pack2(szz, szz);
#pragma unroll
        for (int o = 0; o < 4; o++) zz[j][o] = pack2(z[o], z[o]);
    }

    const ull neg2 = pack2(-2.0f, -2.0f);

    float best[PPT];
    int   bi[PPT];
#pragma unroll
    for (int j = 0; j < PPT; j++) { best[j] = 3.4e38f; bi[j] = 0; }

#pragma unroll 8
    for (int pr = 0; pr < PAIRS; ++pr) {
        const ull* q = (const ull*)(s + pr * 12);  // 48B stride, 16B aligned
        ull m0 = q[0], m1 = q[1], m2 = q[2], m3 = q[3], cc = q[4];
#pragma unroll
        for (int j = 0; j < PPT; j++) {
            // SGEMM-order dot product (mul == fma-with-zero, ascending k)
            ull dot = mul2(zz[j][0], m0);
            dot = fma2(zz[j][1], m1, dot);
            dot = fma2(zz[j][2], m2, dot);
            dot = fma2(zz[j][3], m3, dot);
            // t = szz - 2*dot (2*dot exact => single rounding); d2 = t + scc
            ull t  = fma2(dot, neg2, szz2[j]);
            ull d2 = add2(t, cc);
            float s0, s1;
            unpack2(d2, s0, s1);
            // FMNMX carries the min; FSETP feeds the index SEL only.
            // strict < keeps the earlier index on ties (first-occurrence).
            bool p0 = (s0 < best[j]);
            best[j] = fminf(best[j], s0);
            bi[j] = p0 ? 2 * pr : bi[j];
            bool p1 = (s1 < best[j]);
            best[j] = fminf(best[j], s1);
            bi[j] = p1 ? 2 * pr + 1 : bi[j];
        }
    }

#pragma unroll
    for (int j = 0; j < PPT; j++) {
        int p = pg * (T1 * PPT) + j * T1 + tid;
        g_bi[slice * NPOINTS + p] = make_float2(best[j], __int_as_float(k0 + bi[j]));
    }
}

// ============================================================================
// Kernel 2: per-point 32-way argmin across slices (packed float2 loads),
// gather code, write latent (z + (zq - z)), loss partials via shuffles.
// ============================================================================
__global__ __launch_bounds__(256) void vq_finalize(
    const float* __restrict__ zin,
    const float* __restrict__ Wm,
    const float* __restrict__ bv,
    const float* __restrict__ cb,
    float* __restrict__ out)
{
    __shared__ float wq[16], bb[4];
    __shared__ float wsum[8];
    if (threadIdx.x < 16) wq[threadIdx.x] = __ldg(Wm + threadIdx.x);
    if (threadIdx.x < 4)  bb[threadIdx.x] = __ldg(bv + threadIdx.x);
    __syncthreads();

    const int p  = blockIdx.x * 256 + threadIdx.x;
    const int b  = p >> 12;
    const int hw = p & (HW - 1);

    float z[4];
    compute_z(zin, wq, bb, p, z);

    float bestv = 3.4e38f;
    int   idx   = 0;
#pragma unroll
    for (int sl = 0; sl < NSLICE; sl++) {
        float2 v = g_bi[sl * NPOINTS + p];
        if (v.x < bestv) { bestv = v.x; idx = __float_as_int(v.y); }
    }

    float4 c = ((const float4*)cb)[idx];
    float* ob = out + b * (4 * HW) + hw;
    // straight-through: z + (zq - z), two roundings, as in the reference
    float r0 = __fadd_rn(c.x, -z[0]);
    float r1 = __fadd_rn(c.y, -z[1]);
    float r2 = __fadd_rn(c.z, -z[2]);
    float r3 = __fadd_rn(c.w, -z[3]);
    ob[0]      = __fadd_rn(z[0], r0);
    ob[HW]     = __fadd_rn(z[1], r1);
    ob[2 * HW] = __fadd_rn(z[2], r2);
    ob[3 * HW] = __fadd_rn(z[3], r3);

    float acc = sumsq4(r0, r1, r2, r3);

    // warp shuffle reduce, then one smem round (deterministic order)
#pragma unroll
    for (int o = 16; o > 0; o >>= 1)
        acc += __shfl_down_sync(0xffffffffu, acc, o);
    if ((threadIdx.x & 31) == 0) wsum[threadIdx.x >> 5] = acc;
    __syncthreads();
    if (threadIdx.x == 0) {
        float t = 0.f;
#pragma unroll
        for (int w = 0; w < 8; w++) t += wsum[w];
        g_partial[blockIdx.x] = t;
    }
}

// ============================================================================
// Kernel 3: deterministic final reduction of loss partials.
// q_loss = codebook_loss + BETA*commitment_loss = (1+0.25)*mean((zq-z)^2)
// ============================================================================
__global__ void vq_loss(float* __restrict__ out, int loss_idx)
{
    __shared__ float red[128];
    float a = g_partial[threadIdx.x];  // FBLOCKS == 128
    red[threadIdx.x] = a;
    __syncthreads();
#pragma unroll
    for (int st = 64; st > 0; st >>= 1) {
        if (threadIdx.x < st) red[threadIdx.x] += red[threadIdx.x + st];
        __syncthreads();
    }
    if (threadIdx.x == 0)
        out[loss_idx] = red[0] * (1.25f / (float)(NPOINTS * 4));
}

extern "C" void kernel_launch(void* const* d_in, const int* in_sizes, int n_in,
                              void* d_out, int out_size)
{
    const float* zin = (const float*)d_in[0];  // z_e_in [8,4,64,64]
    const float* Wm  = (const float*)d_in[1];  // pq_w [4,4]
    const float* bv  = (const float*)d_in[2];  // pq_b [4]
    const float* cb  = (const float*)d_in[3];  // codebook [8192,4]
    float* out = (float*)d_out;

    dim3 g1(PGROUPS, NSLICE);
    vq_search<<<g1, T1>>>(zin, Wm, bv, cb);
    vq_finalize<<<FBLOCKS, 256>>>(zin, Wm, bv, cb, out);
    vq_loss<<<1, 128>>>(out, out_size - 1);
}

// round 10
// speedup vs baseline: 1.6692x; 1.0227x over previous
#include <cuda_runtime.h>

typedef unsigned long long ull;

#define NPOINTS 32768
#define HW      4096
#define NCODES  8192
#define NSLICE  32
#define KSLICE  (NCODES / NSLICE)   // 256 codes per slice
#define PAIRS   (KSLICE / 2)        // 128 code-pairs per slice
#define T1      64                  // threads per CTA (2 warps)
#define PPT     4                   // points per thread
#define PGROUPS (NPOINTS / (T1 * PPT))  // 128  -> grid = 4096 CTAs
#define FBLOCKS (NPOINTS / 256)     // 128 finalize blocks

// Scratch (device globals — no allocation allowed in kernel_launch)
__device__ float2 g_bi[NSLICE * NPOINTS];  // (.x = best d2, .y = idx bits)
__device__ float  g_partial[FBLOCKS];

// ---- packed f32x2 helpers (sm_103a); per-lane IEEE rn, same as scalar ----
__device__ __forceinline__ ull fma2(ull a, ull b, ull c) {
    ull d;
    asm("fma.rn.f32x2 %0, %1, %2, %3;" : "=l"(d) : "l"(a), "l"(b), "l"(c));
    return d;
}
__device__ __forceinline__ ull add2(ull a, ull b) {
    ull d;
    asm("add.rn.f32x2 %0, %1, %2;" : "=l"(d) : "l"(a), "l"(b));
    return d;
}
__device__ __forceinline__ ull mul2(ull a, ull b) {
    ull d;
    asm("mul.rn.f32x2 %0, %1, %2;" : "=l"(d) : "l"(a), "l"(b));
    return d;
}
__device__ __forceinline__ ull pack2(float lo, float hi) {
    ull d;
    asm("mov.b64 %0, {%1, %2};" : "=l"(d) : "f"(lo), "f"(hi));
    return d;
}
__device__ __forceinline__ void unpack2(ull v, float& lo, float& hi) {
    asm("mov.b64 {%0, %1}, %2;" : "=f"(lo), "=f"(hi) : "l"(v));
}

// Reference fp32 1x1-conv einsum + bias, XLA/cuBLAS association:
//   dot = ascending-k FFMA chain starting from x0*w0; z = dot + b (bias LAST).
__device__ __forceinline__ void compute_z(
    const float* __restrict__ zin, const float* w /*16*/,
    const float* bb /*4*/, int p, float z[4])
{
    int b = p >> 12, hw = p & (HW - 1);
    const float* base = zin + b * (4 * HW) + hw;
    float x0 = base[0], x1 = base[HW], x2 = base[2 * HW], x3 = base[3 * HW];
#pragma unroll
    for (int o = 0; o < 4; o++) {
        float acc = __fmul_rn(x0, w[o * 4 + 0]);
        acc = __fmaf_rn(x1, w[o * 4 + 1], acc);
        acc = __fmaf_rn(x2, w[o * 4 + 2], acc);
        acc = __fmaf_rn(x3, w[o * 4 + 3], acc);
        z[o] = __fadd_rn(acc, bb[o]);
    }
}

// sum of squares, XLA style: elementwise multiply THEN sequential add (no FMA)
__device__ __forceinline__ float sumsq4(float a, float b, float c, float d) {
    float m0 = __fmul_rn(a, a), m1 = __fmul_rn(b, b);
    float m2 = __fmul_rn(c, c), m3 = __fmul_rn(d, d);
    return __fadd_rn(__fadd_rn(__fadd_rn(m0, m1), m2), m3);
}

// ============================================================================
// Kernel 1: per (point-group, code-slice) CTA — scan 256 codes for 256 points.
// Exact reference fp32 association via a NEGATED-DOUBLED chain:
//   zn = -2z (exact);  chain mul2/fma2 over zn,c  ==  -2*dot with the
//   reference's per-step roundings (rn(-2x) = -2 rn(x), scaling exact);
//   t  = add2(szz, -2dot)  == rn(szz - 2*dot)  (same single rounding)
//   d2 = add2(t, scc)
// One fewer 3-source packed FMA per pair (rt=3 from RF banking) -> higher issue.
// Argmin: FMNMX carries the min; update detected by ISETP.NE on result bits
// (value changed iff strictly smaller; ties keep earlier index).
// smem pair layout (12 floats = 48B): [2d+ln] = c_{2pr+ln}[d], [8+ln] = ||c||^2
// ============================================================================
__global__ __launch_bounds__(T1) void vq_search(
    const float* __restrict__ zin,   // [8,4,64,64]
    const float* __restrict__ Wm,    // [4,4]
    const float* __restrict__ bv,    // [4]
    const float* __restrict__ cb)    // [8192,4]
{
    __shared__ float s[PAIRS * 12];
    __shared__ float wq[16], bb[4];
    const int tid   = threadIdx.x;
    const int pg    = blockIdx.x;   // 0..127
    const int slice = blockIdx.y;   // 0..31
    const int k0    = slice * KSLICE;

    if (tid < 16) wq[tid] = __ldg(Wm + tid);
    if (tid < 4)  bb[tid] = __ldg(bv + tid);

    // Build codebook slice + fp32 |c|^2 (mul-then-add order) in smem
#pragma unroll
    for (int kk = tid; kk < KSLICE; kk += T1) {
        float4 c = ((const float4*)cb)[k0 + kk];
        int pr = kk >> 1, ln = kk & 1;
        float* d = s + pr * 12;
        d[0 + ln] = c.x;
        d[2 + ln] = c.y;
        d[4 + ln] = c.z;
        d[6 + ln] = c.w;
        d[8 + ln] = sumsq4(c.x, c.y, c.z, c.w);
    }
    __syncthreads();

    ull zn[PPT][4];   // -2*z_d duplicated in both halves (exact scaling)
    ull szz2[PPT];    // ||z||^2 duplicated
#pragma unroll
    for (int j = 0; j < PPT; j++) {
        int p = pg * (T1 * PPT) + j * T1 + tid;  // coalesced over tid
        float z[4];
        compute_z(zin, wq, bb, p, z);
        float szz = sumsq4(z[0], z[1], z[2], z[3]);
        szz2[j] = pack2(szz, szz);
#pragma unroll
        for (int o = 0; o < 4; o++) {
            float m = -2.0f * z[o];   // exact (power-of-two scale + negate)
            zn[j][o] = pack2(m, m);
        }
    }

    float best[PPT];
    int   bi[PPT];
#pragma unroll
    for (int j = 0; j < PPT; j++) { best[j] = 3.4e38f; bi[j] = 0; }

#pragma unroll 8
    for (int pr = 0; pr < PAIRS; ++pr) {
        const ull* q = (const ull*)(s + pr * 12);  // 48B stride, 16B aligned
        ull m0 = q[0], m1 = q[1], m2 = q[2], m3 = q[3], cc = q[4];
        const int ke = 2 * pr;
#pragma unroll
        for (int j = 0; j < PPT; j++) {
            // chain over (-2z, c): acc == -2*dot with reference roundings
            ull acc = mul2(zn[j][0], m0);
            acc = fma2(zn[j][1], m1, acc);
            acc = fma2(zn[j][2], m2, acc);
            acc = fma2(zn[j][3], m3, acc);
            ull t  = add2(szz2[j], acc);   // rn(szz - 2*dot)
            ull d2 = add2(t, cc);          // + ||c||^2
            float s0, s1;
            unpack2(d2, s0, s1);
            // FMNMX carries the min; ISETP.NE on bits detects strict improve.
            float nb0 = fminf(best[j], s0);
            bool  c0  = (__float_as_int(nb0) != __float_as_int(best[j]));
            bi[j]   = c0 ? ke : bi[j];
            best[j] = nb0;
            float nb1 = fminf(best[j], s1);
            bool  c1  = (__float_as_int(nb1) != __float_as_int(best[j]));
            bi[j]   = c1 ? ke + 1 : bi[j];
            best[j] = nb1;
        }
    }

#pragma unroll
    for (int j = 0; j < PPT; j++) {
        int p = pg * (T1 * PPT) + j * T1 + tid;
        g_bi[slice * NPOINTS + p] = make_float2(best[j], __int_as_float(k0 + bi[j]));
    }
}

// ============================================================================
// Kernel 2: per-point 32-way argmin across slices (packed float2 loads),
// gather code, write latent (z + (zq - z)), loss partials via shuffles.
// ============================================================================
__global__ __launch_bounds__(256) void vq_finalize(
    const float* __restrict__ zin,
    const float* __restrict__ Wm,
    const float* __restrict__ bv,
    const float* __restrict__ cb,
    float* __restrict__ out)
{
    __shared__ float wq[16], bb[4];
    __shared__ float wsum[8];
    if (threadIdx.x < 16) wq[threadIdx.x] = __ldg(Wm + threadIdx.x);
    if (threadIdx.x < 4)  bb[threadIdx.x] = __ldg(bv + threadIdx.x);
    __syncthreads();

    const int p  = blockIdx.x * 256 + threadIdx.x;
    const int b  = p >> 12;
    const int hw = p & (HW - 1);

    float z[4];
    compute_z(zin, wq, bb, p, z);

    float bestv = 3.4e38f;
    int   idx   = 0;
#pragma unroll
    for (int sl = 0; sl < NSLICE; sl++) {
        float2 v = g_bi[sl * NPOINTS + p];
        if (v.x < bestv) { bestv = v.x; idx = __float_as_int(v.y); }
    }

    float4 c = ((const float4*)cb)[idx];
    float* ob = out + b * (4 * HW) + hw;
    // straight-through: z + (zq - z), two roundings, as in the reference
    float r0 = __fadd_rn(c.x, -z[0]);
    float r1 = __fadd_rn(c.y, -z[1]);
    float r2 = __fadd_rn(c.z, -z[2]);
    float r3 = __fadd_rn(c.w, -z[3]);
    ob[0]      = __fadd_rn(z[0], r0);
    ob[HW]     = __fadd_rn(z[1], r1);
    ob[2 * HW] = __fadd_rn(z[2], r2);
    ob[3 * HW] = __fadd_rn(z[3], r3);

    float acc = sumsq4(r0, r1, r2, r3);

    // warp shuffle reduce, then one smem round (deterministic order)
#pragma unroll
    for (int o = 16; o > 0; o >>= 1)
        acc += __shfl_down_sync(0xffffffffu, acc, o);
    if ((threadIdx.x & 31) == 0) wsum[threadIdx.x >> 5] = acc;
    __syncthreads();
    if (threadIdx.x == 0) {
        float t = 0.f;
#pragma unroll
        for (int w = 0; w < 8; w++) t += wsum[w];
        g_partial[blockIdx.x] = t;
    }
}

// ============================================================================
// Kernel 3: deterministic final reduction of loss partials.
// q_loss = codebook_loss + BETA*commitment_loss = (1+0.25)*mean((zq-z)^2)
// ============================================================================
__global__ void vq_loss(float* __restrict__ out, int loss_idx)
{
    __shared__ float red[128];
    float a = g_partial[threadIdx.x];  // FBLOCKS == 128
    red[threadIdx.x] = a;
    __syncthreads();
#pragma unroll
    for (int st = 64; st > 0; st >>= 1) {
        if (threadIdx.x < st) red[threadIdx.x] += red[threadIdx.x + st];
        __syncthreads();
    }
    if (threadIdx.x == 0)
        out[loss_idx] = red[0] * (1.25f / (float)(NPOINTS * 4));
}

extern "C" void kernel_launch(void* const* d_in, const int* in_sizes, int n_in,
                              void* d_out, int out_size)
{
    const float* zin = (const float*)d_in[0];  // z_e_in [8,4,64,64]
    const float* Wm  = (const float*)d_in[1];  // pq_w [4,4]
    const float* bv  = (const float*)d_in[2];  // pq_b [4]
    const float* cb  = (const float*)d_in[3];  // codebook [8192,4]
    float* out = (float*)d_out;

    dim3 g1(PGROUPS, NSLICE);
    vq_search<<<g1, T1>>>(zin, Wm, bv, cb);
    vq_finalize<<<FBLOCKS, 256>>>(zin, Wm, bv, cb, out);
    vq_loss<<<1, 128>>>(out, out_size - 1);
}